// round 2
// baseline (speedup 1.0000x reference)
#include <cuda_runtime.h>

// 2-layer LSTM (H=50), T=65536 strictly-serial steps, single persistent CTA.
// 3-barrier software-pipelined step:
//   Phase0 (gate warps): acc2 = b2 + W_hh2 @ h2(s-1)            [runs || Phase1]
//   Phase1 (unit warps): err update, gates1 finish (+w7*err), cell1 -> h1(s)
//   BAR_A
//   Phase2 (gate warps): g2(s) = acc2 + W_ih2 @ h1(s)  -> sg2
//                        partial1(s+1) = b1 + W_ih1@x(s+1) + W_hh1@h1(s) -> sg1p
//   BAR_B
//   Phase3 (unit warps): cell2 -> h2(s), y contrib via SMEM atomic, cache x7
//   BAR_C
// Thread layout: 320 threads. Warps 0-7 = gate warps (lanes 0-24 own row
// w*25+l of the 200 gate rows) -> exactly 2 gate warps per SMSP. Warps 8-9 =
// unit warps (threads 256-305 own units 0-49), disjoint from gates so the
// Phase0||Phase1 overlap is real. Activations use tanh.approx.f32.

#define HDIM     50
#define INP      8
#define CHUNK    1024
#define NTHREADS 320
#define UBASE    256

typedef unsigned long long u64;

__device__ __forceinline__ u64 pk2(float lo, float hi) {
    u64 r; asm("mov.b64 %0, {%1,%2};" : "=l"(r) : "f"(lo), "f"(hi)); return r;
}
__device__ __forceinline__ float2 upk2(u64 v) {
    float2 f; asm("mov.b64 {%0,%1}, %2;" : "=f"(f.x), "=f"(f.y) : "l"(v)); return f;
}
__device__ __forceinline__ u64 ffma2(u64 a, u64 b, u64 c) {
    u64 d; asm("fma.rn.f32x2 %0, %1, %2, %3;" : "=l"(d) : "l"(a), "l"(b), "l"(c)); return d;
}
__device__ __forceinline__ float tanha(float x) {
    float r; asm("tanh.approx.f32 %0, %1;" : "=f"(r) : "f"(x)); return r;
}
__device__ __forceinline__ float sig(float x) {
    return fmaf(tanha(0.5f * x), 0.5f, 0.5f);
}

__global__ __launch_bounds__(NTHREADS, 1)
void lstm_pipe_kernel(const float* __restrict__ input_seq,
                      const float* __restrict__ W_ih1, const float* __restrict__ W_hh1,
                      const float* __restrict__ b_ih1, const float* __restrict__ b_hh1,
                      const float* __restrict__ W_ih2, const float* __restrict__ W_hh2,
                      const float* __restrict__ b_ih2, const float* __restrict__ b_hh2,
                      const float* __restrict__ W_out, const float* __restrict__ b_out,
                      float* __restrict__ out, int T)
{
    __shared__ __align__(16) float sh1[56];            // h1 state (padded, [50..] = 0)
    __shared__ __align__(16) float sh2[56];            // h2 state (padded)
    __shared__ __align__(16) float sg1p[200];          // partial gates1 (next step)
    __shared__ __align__(16) float sg2[200];           // gates2 (this step)
    __shared__ float sy[3];                            // rotating y accumulators
    __shared__ __align__(16) float xbuf[(CHUNK + 1) * INP];

    const int t = threadIdx.x;
    const int w = t >> 5;
    const int l = t & 31;
    const bool gate_warp = (w < 8);
    const bool is_gate = gate_warp && (l < 25);
    const int grow = is_gate ? (w * 25 + l) : 0;       // clamped for inactive lanes
    const bool is_unit = (t >= UBASE) && (t < UBASE + HDIM);
    const int u = is_unit ? (t - UBASE) : 0;

    // ---- one-time: gate-row weights into registers (f32x2, zero-padded to 52)
    u64 wi1[4], wh1[26], wi2[26], wh2[26];
    float bb1, bb2;
    {
        const float* r = W_ih1 + grow * INP;
        #pragma unroll
        for (int j = 0; j < 4; ++j) wi1[j] = pk2(r[2*j], r[2*j+1]);
        const float* r2 = W_hh1 + grow * HDIM;
        const float* r3 = W_ih2 + grow * HDIM;
        const float* r4 = W_hh2 + grow * HDIM;
        #pragma unroll
        for (int j = 0; j < 25; ++j) {
            wh1[j] = pk2(r2[2*j], r2[2*j+1]);
            wi2[j] = pk2(r3[2*j], r3[2*j+1]);
            wh2[j] = pk2(r4[2*j], r4[2*j+1]);
        }
        wh1[25] = 0ULL; wi2[25] = 0ULL; wh2[25] = 0ULL;  // pad (reads sh[48..51])
        bb1 = b_ih1[grow] + b_hh1[grow];
        bb2 = b_ih2[grow] + b_hh2[grow];
    }
    // ---- unit-thread constants
    const float wi7_0 = W_ih1[(u +   0) * INP + 7];
    const float wi7_1 = W_ih1[(u +  50) * INP + 7];
    const float wi7_2 = W_ih1[(u + 100) * INP + 7];
    const float wi7_3 = W_ih1[(u + 150) * INP + 7];
    const float wout_u = W_out[u];
    const float bo = b_out[0];

    // ---- init shared state
    for (int i = t; i < 56; i += NTHREADS) { sh1[i] = 0.0f; sh2[i] = 0.0f; }
    if (t < 3) sy[t] = (t == 2) ? 0.0f : bo;   // slot2 read as y(-1)=0; slots 0,1 preseeded

    float c1 = 0.0f, c2 = 0.0f, err = 0.0f, x7prev = 0.0f;
    int ridx = 2, widx = 0;                    // read slot (s+2)%3, write slot s%3

    __syncthreads();

    #pragma unroll 1
    for (int s = 0; s < T; ++s) {
        const int lo = s & (CHUNK - 1);
        if (lo == 0) {
            // stage CHUNK+1 steps (overlap: x(s+CHUNK) needed by Phase2 of last step)
            const float4* src = (const float4*)(input_seq + (size_t)s * INP);
            float4* dst = (float4*)xbuf;
            int n4 = (CHUNK + 1) * 2;
            int rem4 = (T - s) * 2;
            if (rem4 < n4) n4 = rem4;
            for (int i = t; i < n4; i += NTHREADS) dst[i] = src[i];
            __syncthreads();
        }
        if (s == 0) {
            // bootstrap sg1p(0) = b1 + W_ih1 @ x(0)   (h1(-1)=0)
            if (gate_warp) {
                float4 xa = *(const float4*)(xbuf);
                float4 xb = *(const float4*)(xbuf + 4);
                u64 a0 = ffma2(wi1[0], pk2(xa.x, xa.y), pk2(bb1, 0.0f));
                u64 a1 = ffma2(wi1[1], pk2(xa.z, xa.w), pk2(0.0f, 0.0f));
                a0 = ffma2(wi1[2], pk2(xb.x, xb.y), a0);
                a1 = ffma2(wi1[3], pk2(xb.z, 0.0f), a1);
                if (is_gate) {
                    float2 f0 = upk2(a0), f1 = upk2(a1);
                    sg1p[grow] = (f0.x + f1.x) + (f0.y + f1.y);
                }
            }
            __syncthreads();
        }

        u64 g20, g21;   // gates2 accumulator, carried Phase0 -> Phase2
        if (gate_warp) {
            // ---- Phase0: acc2 = b2 + W_hh2 @ h2(s-1)   (overlaps Phase1)
            g20 = pk2(bb2, 0.0f); g21 = pk2(0.0f, 0.0f);
            const float4* hv = (const float4*)sh2;
            #pragma unroll
            for (int j = 0; j < 13; ++j) {
                float4 h = hv[j];
                g20 = ffma2(wh2[2*j],     pk2(h.x, h.y), g20);
                g21 = ffma2(wh2[2*j + 1], pk2(h.z, h.w), g21);
            }
        } else if (is_unit) {
            // ---- Phase1: err update, gates1 finish, cell1
            float y = sy[ridx];                       // y(s-1), includes b_out
            err = 0.9f * err + 0.1f * (x7prev - y);
            float ga = sg1p[u]       + wi7_0 * err;
            float gb = sg1p[u +  50] + wi7_1 * err;
            float gc = sg1p[u + 100] + wi7_2 * err;
            float gd = sg1p[u + 150] + wi7_3 * err;
            float I = sig(ga), F = sig(gb), G = tanha(gc), O = sig(gd);
            c1 = F * c1 + I * G;
            sh1[u] = O * tanha(c1);
            if (u == 0 && s > 0) out[s - 1] = y;
        }
        __syncthreads();   // BAR_A: h1(s) ready

        if (gate_warp) {
            // ---- Phase2: finish gates2(s) and partial1(s+1); h1 loaded once
            u64 a0 = pk2(bb1, 0.0f), a1 = pk2(0.0f, 0.0f);
            const float4* hv = (const float4*)sh1;
            #pragma unroll
            for (int j = 0; j < 13; ++j) {
                float4 h = hv[j];
                u64 hl = pk2(h.x, h.y), hh = pk2(h.z, h.w);
                a0  = ffma2(wh1[2*j],     hl, a0);
                a1  = ffma2(wh1[2*j + 1], hh, a1);
                g20 = ffma2(wi2[2*j],     hl, g20);
                g21 = ffma2(wi2[2*j + 1], hh, g21);
            }
            const float* xn = &xbuf[(lo + 1) * INP];   // x(s+1) (overlap slot at chunk end)
            float4 xa = *(const float4*)(xn);
            float4 xb = *(const float4*)(xn + 4);
            a0 = ffma2(wi1[0], pk2(xa.x, xa.y), a0);
            a1 = ffma2(wi1[1], pk2(xa.z, xa.w), a1);
            a0 = ffma2(wi1[2], pk2(xb.x, xb.y), a0);
            a1 = ffma2(wi1[3], pk2(xb.z, 0.0f), a1);   // err slot added in Phase1
            if (is_gate) {
                float2 f0 = upk2(a0), f1 = upk2(a1);
                sg1p[grow] = (f0.x + f1.x) + (f0.y + f1.y);
                float2 q0 = upk2(g20), q1 = upk2(g21);
                sg2[grow] = (q0.x + q1.x) + (q0.y + q1.y);
                if (grow == 0) sy[ridx] = bo;          // reseed just-read slot for step s+2
            }
        }
        __syncthreads();   // BAR_B: gates2 ready

        if (is_unit) {
            // ---- Phase3: cell2, y contribution, cache x7(s)
            float ga = sg2[u], gb = sg2[u + 50], gc = sg2[u + 100], gd = sg2[u + 150];
            float I = sig(ga), F = sig(gb), G = tanha(gc), O = sig(gd);
            c2 = F * c2 + I * G;
            float h2 = O * tanha(c2);
            sh2[u] = h2;
            atomicAdd(&sy[widx], wout_u * h2);
            x7prev = xbuf[lo * INP + 7];
        }
        ridx = (ridx == 2) ? 0 : ridx + 1;
        widx = (widx == 2) ? 0 : widx + 1;
        __syncthreads();   // BAR_C: h2(s), y(s), sg1p(s+1) ready
    }

    // final output: y(T-1) sits in the slot ridx now points at ((T-1)%3)
    if (t == UBASE) out[T - 1] = sy[ridx];
}

extern "C" void kernel_launch(void* const* d_in, const int* in_sizes, int n_in,
                              void* d_out, int out_size) {
    const int T = in_sizes[0] / INP;
    lstm_pipe_kernel<<<1, NTHREADS>>>(
        (const float*)d_in[0],
        (const float*)d_in[1], (const float*)d_in[2],
        (const float*)d_in[3], (const float*)d_in[4],
        (const float*)d_in[5], (const float*)d_in[6],
        (const float*)d_in[7], (const float*)d_in[8],
        (const float*)d_in[9], (const float*)d_in[10],
        (float*)d_out, T);
}

// round 3
// speedup vs baseline: 1.1833x; 1.1833x over previous
#include <cuda_runtime.h>

// 2-layer LSTM (H=50), T=65536 strictly-serial steps, one persistent CTA.
// Split-K: every gate row's dot products are split across two thread groups
// (A: h-dims 0..23, B: h-dims 24..49) so per-thread weight storage is ~86
// regs (no spills at 512 threads) and FFMA2 chains are depth 6-7.
//
// Per step (3 syncthreads):
//   P0 gates : q = [bb2] + W_hh2_half @ h2(s-1)        (overlaps P1)
//   P1 units : err; gates1 = a1A+a1B+w7*err; cell1 -> h1(s)
//   BAR_A
//   P2 gates : g2_half = q + W_ih2_half @ h1(s) -> g2A/g2B
//   BAR_B
//   P3 units : cell2 -> h2(s); y via smem atomicAdd; cache x7(s)
//      gates : a1_half(s+1) = [bb1 + W_ih1 @ x(s+1)] + W_hh1_half @ h1(s)
//   BAR_C

#define HDIM     50
#define INP      8
#define CHUNK    1024
#define NTHREADS 512

typedef unsigned long long u64;

__device__ __forceinline__ u64 pk2(float lo, float hi) {
    u64 r; asm("mov.b64 %0, {%1,%2};" : "=l"(r) : "f"(lo), "f"(hi)); return r;
}
__device__ __forceinline__ float2 upk2(u64 v) {
    float2 f; asm("mov.b64 {%0,%1}, %2;" : "=f"(f.x), "=f"(f.y) : "l"(v)); return f;
}
__device__ __forceinline__ u64 ffma2(u64 a, u64 b, u64 c) {
    u64 d; asm("fma.rn.f32x2 %0, %1, %2, %3;" : "=l"(d) : "l"(a), "l"(b), "l"(c)); return d;
}
__device__ __forceinline__ float tanha(float x) {
    float r; asm("tanh.approx.f32 %0, %1;" : "=f"(r) : "f"(x)); return r;
}
__device__ __forceinline__ float sig(float x) {
    return fmaf(tanha(0.5f * x), 0.5f, 0.5f);
}

__global__ __launch_bounds__(NTHREADS, 1)
void lstm_splitk_kernel(const float* __restrict__ input_seq,
                        const float* __restrict__ W_ih1, const float* __restrict__ W_hh1,
                        const float* __restrict__ b_ih1, const float* __restrict__ b_hh1,
                        const float* __restrict__ W_ih2, const float* __restrict__ W_hh2,
                        const float* __restrict__ b_ih2, const float* __restrict__ b_hh2,
                        const float* __restrict__ W_out, const float* __restrict__ b_out,
                        float* __restrict__ out, int T)
{
    __shared__ __align__(16) float sh1[52];     // h1(s)
    __shared__ __align__(16) float sh2[52];     // h2(s)
    __shared__ __align__(16) float g2A[200];    // gates2 partial (K 0..23)
    __shared__ __align__(16) float g2B[200];    // gates2 partial (K 24..49)
    __shared__ __align__(16) float a1A[200];    // gates1(s+1) partial A (+bias+x-dot)
    __shared__ __align__(16) float a1B[200];    // gates1(s+1) partial B
    __shared__ float sy[2];                     // ping-pong y accumulators
    __shared__ __align__(16) float xbuf[(CHUNK + 2) * INP];

    const int t = threadIdx.x;
    const int w = t >> 5;
    const int l = t & 31;
    const bool grpA = (w < 7);
    const bool grpB = (w >= 7) && (w < 14);
    const bool gateT = grpA || grpB;
    const int rraw = grpA ? (w * 32 + l) : ((w - 7) * 32 + l);
    const bool gact = gateT && (rraw < 200);
    const int row = gact ? rraw : 199;
    const bool unitT = (w >= 14);
    const int uraw = (w - 14) * 32 + l;
    const bool uact = unitT && (uraw < HDIM);
    const int u = (uact ? uraw : HDIM - 1);

    // ---- per-thread weights (f32x2 packed). A: pairs 0..11, B: pairs 12..24.
    // wWH2 / wWI2 / wWH1 hold this thread's K-half of W_hh2 / W_ih2 / W_hh1 rows.
    u64 wWH2[13], wWI2[13], wWH1[13], wx[4];
    float bbA = 0.0f, bbB = 0.0f;   // A: bb2 ; also A gets bb1+x-dot duty
    if (gateT) {
        const int kb = grpA ? 0 : 12;          // pair base
        const int np = grpA ? 12 : 13;
        const float* r2 = W_hh2 + row * HDIM + 2 * kb;
        const float* r3 = W_ih2 + row * HDIM + 2 * kb;
        const float* r4 = W_hh1 + row * HDIM + 2 * kb;
        #pragma unroll
        for (int j = 0; j < 13; ++j) {
            if (j < np) {
                wWH2[j] = pk2(r2[2*j], r2[2*j+1]);
                wWI2[j] = pk2(r3[2*j], r3[2*j+1]);
                wWH1[j] = pk2(r4[2*j], r4[2*j+1]);
            } else { wWH2[j] = 0; wWI2[j] = 0; wWH1[j] = 0; }
        }
        if (grpA) {
            const float* r1 = W_ih1 + row * INP;
            wx[0] = pk2(r1[0], r1[1]);
            wx[1] = pk2(r1[2], r1[3]);
            wx[2] = pk2(r1[4], r1[5]);
            wx[3] = pk2(r1[6], 0.0f);          // 8th input (err) handled by units
            bbA = b_ih2[row] + b_hh2[row];     // bb2 (into A's P0 accumulator)
            bbB = b_ih1[row] + b_hh1[row];     // bb1 (into A's a1 partial)
        }
    }
    // ---- unit-thread constants
    const float wi7_0 = W_ih1[(u +   0) * INP + 7];
    const float wi7_1 = W_ih1[(u +  50) * INP + 7];
    const float wi7_2 = W_ih1[(u + 100) * INP + 7];
    const float wi7_3 = W_ih1[(u + 150) * INP + 7];
    const float wout_u = W_out[u];
    const float bo = b_out[0];

    for (int i = t; i < 52; i += NTHREADS) { sh1[i] = 0.0f; sh2[i] = 0.0f; }
    if (t == 0) { sy[0] = bo; sy[1] = 0.0f; }   // sy[1] read as y(-1)=0 at s=0

    float c1 = 0.0f, c2 = 0.0f, err = 0.0f, x7prev = 0.0f;

    __syncthreads();

    #pragma unroll 1
    for (int s = 0; s < T; ++s) {
        const int lo = s & (CHUNK - 1);
        if (lo == 0) {
            // stage CHUNK+1 steps of input (overlap slot for x(s+1) at chunk end)
            const float4* src = (const float4*)(input_seq + (size_t)s * INP);
            float4* dst = (float4*)xbuf;
            int n4 = (CHUNK + 1) * 2;
            int rem4 = (T - s) * 2;
            if (rem4 < n4) n4 = rem4;
            for (int i = t; i < n4; i += NTHREADS) dst[i] = src[i];
            __syncthreads();
            if (s == 0) {
                // bootstrap: a1(0) = bb1 + W_ih1 @ x(0)  (h1(-1)=0)
                if (gateT) {
                    if (grpA) {
                        float4 xa = *(const float4*)(xbuf);
                        float4 xb = *(const float4*)(xbuf + 4);
                        u64 a0 = ffma2(wx[0], pk2(xa.x, xa.y), pk2(bbB, 0.0f));
                        u64 a1 = ffma2(wx[1], pk2(xa.z, xa.w), pk2(0.0f, 0.0f));
                        a0 = ffma2(wx[2], pk2(xb.x, xb.y), a0);
                        a1 = ffma2(wx[3], pk2(xb.z, 0.0f), a1);
                        float2 f0 = upk2(a0), f1 = upk2(a1);
                        if (gact) a1A[row] = (f0.x + f1.x) + (f0.y + f1.y);
                    } else {
                        if (gact) a1B[row] = 0.0f;
                    }
                }
                __syncthreads();
            }
        }

        u64 q0, q1;   // gates2 half-accumulator, carried P0 -> P2
        if (gateT) {
            // ---- P0: q = [bb2] + W_hh2_half @ h2(s-1)   (overlaps P1)
            q0 = pk2(bbA, 0.0f); q1 = pk2(0.0f, 0.0f);
            const float4* hv = (const float4*)sh2;
            if (grpA) {
                #pragma unroll
                for (int j = 0; j < 6; ++j) {
                    float4 h = hv[j];
                    q0 = ffma2(wWH2[2*j],     pk2(h.x, h.y), q0);
                    q1 = ffma2(wWH2[2*j + 1], pk2(h.z, h.w), q1);
                }
            } else {
                #pragma unroll
                for (int j = 0; j < 6; ++j) {
                    float4 h = hv[6 + j];
                    q0 = ffma2(wWH2[2*j],     pk2(h.x, h.y), q0);
                    q1 = ffma2(wWH2[2*j + 1], pk2(h.z, h.w), q1);
                }
                q0 = ffma2(wWH2[12], ((const u64*)sh2)[24], q0);
            }
        } else {
            // ---- P1 (units): err update, gates1 finish, cell1
            float y = sy[(s + 1) & 1];               // y(s-1)
            err = 0.9f * err + 0.1f * (x7prev - y);
            float ga = (a1A[u]       + a1B[u])       + wi7_0 * err;
            float gb = (a1A[u +  50] + a1B[u +  50]) + wi7_1 * err;
            float gc = (a1A[u + 100] + a1B[u + 100]) + wi7_2 * err;
            float gd = (a1A[u + 150] + a1B[u + 150]) + wi7_3 * err;
            float I = sig(ga), F = sig(gb), G = tanha(gc), O = sig(gd);
            c1 = F * c1 + I * G;
            float h1v = O * tanha(c1);
            if (uact) sh1[u] = h1v;
            if (uact && u == 0 && s > 0) out[s - 1] = y;
        }
        __syncthreads();   // BAR_A: h1(s) ready

        if (gateT) {
            // ---- P2: g2_half = q + W_ih2_half @ h1(s)
            const float4* hv = (const float4*)sh1;
            if (grpA) {
                #pragma unroll
                for (int j = 0; j < 6; ++j) {
                    float4 h = hv[j];
                    q0 = ffma2(wWI2[2*j],     pk2(h.x, h.y), q0);
                    q1 = ffma2(wWI2[2*j + 1], pk2(h.z, h.w), q1);
                }
                float2 f0 = upk2(q0), f1 = upk2(q1);
                if (gact) g2A[row] = (f0.x + f1.x) + (f0.y + f1.y);
                if (t == 6 * 32 + 31) sy[s & 1] = bo;   // reseed write slot
            } else {
                #pragma unroll
                for (int j = 0; j < 6; ++j) {
                    float4 h = hv[6 + j];
                    q0 = ffma2(wWI2[2*j],     pk2(h.x, h.y), q0);
                    q1 = ffma2(wWI2[2*j + 1], pk2(h.z, h.w), q1);
                }
                q0 = ffma2(wWI2[12], ((const u64*)sh1)[24], q0);
                float2 f0 = upk2(q0), f1 = upk2(q1);
                if (gact) g2B[row] = (f0.x + f1.x) + (f0.y + f1.y);
            }
        }
        __syncthreads();   // BAR_B: gates2 ready

        if (gateT) {
            // ---- P3 (gates): a1_half(s+1), fully off the critical path
            const float4* hv = (const float4*)sh1;
            if (grpA) {
                const float* xn = &xbuf[(lo + 1) * INP];
                float4 xa = *(const float4*)(xn);
                float4 xb = *(const float4*)(xn + 4);
                u64 a0 = ffma2(wx[0], pk2(xa.x, xa.y), pk2(bbB, 0.0f));
                u64 a1 = ffma2(wx[1], pk2(xa.z, xa.w), pk2(0.0f, 0.0f));
                a0 = ffma2(wx[2], pk2(xb.x, xb.y), a0);
                a1 = ffma2(wx[3], pk2(xb.z, 0.0f), a1);
                #pragma unroll
                for (int j = 0; j < 6; ++j) {
                    float4 h = hv[j];
                    a0 = ffma2(wWH1[2*j],     pk2(h.x, h.y), a0);
                    a1 = ffma2(wWH1[2*j + 1], pk2(h.z, h.w), a1);
                }
                float2 f0 = upk2(a0), f1 = upk2(a1);
                if (gact) a1A[row] = (f0.x + f1.x) + (f0.y + f1.y);
            } else {
                u64 a0 = pk2(0.0f, 0.0f), a1 = pk2(0.0f, 0.0f);
                #pragma unroll
                for (int j = 0; j < 6; ++j) {
                    float4 h = hv[6 + j];
                    a0 = ffma2(wWH1[2*j],     pk2(h.x, h.y), a0);
                    a1 = ffma2(wWH1[2*j + 1], pk2(h.z, h.w), a1);
                }
                a0 = ffma2(wWH1[12], ((const u64*)sh1)[24], a0);
                float2 f0 = upk2(a0), f1 = upk2(a1);
                if (gact) a1B[row] = (f0.x + f1.x) + (f0.y + f1.y);
            }
        } else {
            // ---- P3 (units): cell2, h2, y contribution
            float ga = g2A[u]       + g2B[u];
            float gb = g2A[u +  50] + g2B[u +  50];
            float gc = g2A[u + 100] + g2B[u + 100];
            float gd = g2A[u + 150] + g2B[u + 150];
            float I = sig(ga), F = sig(gb), G = tanha(gc), O = sig(gd);
            c2 = F * c2 + I * G;
            float h2v = O * tanha(c2);
            if (uact) {
                sh2[u] = h2v;
                atomicAdd(&sy[s & 1], wout_u * h2v);
            }
            x7prev = xbuf[lo * INP + 7];
        }
        __syncthreads();   // BAR_C: h2(s), y(s), a1(s+1) ready
    }

    if (unitT && uact && u == 0) out[T - 1] = sy[(T - 1) & 1];
}

extern "C" void kernel_launch(void* const* d_in, const int* in_sizes, int n_in,
                              void* d_out, int out_size) {
    const int T = in_sizes[0] / INP;
    lstm_splitk_kernel<<<1, NTHREADS>>>(
        (const float*)d_in[0],
        (const float*)d_in[1], (const float*)d_in[2],
        (const float*)d_in[3], (const float*)d_in[4],
        (const float*)d_in[5], (const float*)d_in[6],
        (const float*)d_in[7], (const float*)d_in[8],
        (const float*)d_in[9], (const float*)d_in[10],
        (float*)d_out, T);
}